// round 16
// baseline (speedup 1.0000x reference)
#include <cuda_runtime.h>

// StoutSmearSlice: 24^4 lattice, 4 dirs, 3x3 complex links (separate re/im fp32).
// MU=0, update EVEN parity sites of dir 0; everything else is a copy.
//
// Round 16 = R14/R15 + region-affine copy fusion:
// Each compute block copies dirs1-3 for ITS OWN contiguous 256-site range
// (the same rows its staple gathers just pulled through L1/L2 -> copy loads
// hit hot lines instead of re-reading through L2). Dedicated copy role is
// deleted entirely: grid 4374 -> 1296 blocks.
//  - dir0 even: stout result;  dir0 odd: partner-store trick (R14)
//  - dirs1-3: per-block region loop, 3*576 float4 loads + interleave stores
//  - Taylor 8 terms, evict-first output stores (R11/R14)

#define IDX9(d,t,z,y,x) ((((((d)*24+(t))*24+(z))*24+(y))*24+(x))*9)

static const int NSITE  = 24 * 24 * 24 * 12;          // even sites = 165888
static const int NCB    = NSITE / 128;                // 1296 compute blocks
static const int DIR_F  = 24 * 24 * 24 * 24 * 9;      // floats per direction
static const int DIR_F4 = DIR_F / 4;                  // float4s per direction

typedef unsigned long long c64;   // packed {lo=re, hi=im} fp32 pair

__device__ __forceinline__ c64 pk(float lo, float hi) {
    c64 r; asm("mov.b64 %0,{%1,%2};" : "=l"(r) : "f"(lo), "f"(hi)); return r;
}
__device__ __forceinline__ void upk(c64 v, float &lo, float &hi) {
    asm("mov.b64 {%0,%1},%2;" : "=f"(lo), "=f"(hi) : "l"(v));
}
__device__ __forceinline__ c64 fma2(c64 a, c64 b, c64 c) {
    c64 d; asm("fma.rn.f32x2 %0,%1,%2,%3;" : "=l"(d) : "l"(a), "l"(b), "l"(c));
    return d;
}
__device__ __forceinline__ c64 mul2(c64 a, c64 b) {
    c64 d; asm("mul.rn.f32x2 %0,%1,%2;" : "=l"(d) : "l"(a), "l"(b)); return d;
}

struct C3 { c64 m[9]; };

// Windowed load: base b is 4B-aligned; a = b&~1 is 8B-aligned and [a, a+10)
// covers elements [b, b+9). 5 LDG.64 per array + select.
__device__ __forceinline__ void mload(C3 &A, const float* __restrict__ re,
                                      const float* __restrict__ im, int b) {
    int a = b & ~1;
    bool p = (b & 1) != 0;
    const float2* r2 = (const float2*)(re + a);
    const float2* i2 = (const float2*)(im + a);
    float fr[10], fi[10];
#pragma unroll
    for (int j = 0; j < 5; j++) {
        float2 vr = r2[j], vi = i2[j];
        fr[2*j] = vr.x; fr[2*j+1] = vr.y;
        fi[2*j] = vi.x; fi[2*j+1] = vi.y;
    }
#pragma unroll
    for (int i = 0; i < 9; i++)
        A.m[i] = pk(p ? fr[i+1] : fr[i], p ? fi[i+1] : fi[i]);
}

// MODE: 0 = A@B, 1 = A@B^dag, 2 = A^dag@B
template <int MODE>
__device__ __forceinline__ void cmul(C3 &C, const C3 &A, const C3 &B) {
#pragma unroll
    for (int r = 0; r < 3; r++) {
        float ar[3], ai[3];
#pragma unroll
        for (int k = 0; k < 3; k++)
            upk(A.m[MODE == 2 ? k * 3 + r : r * 3 + k], ar[k], ai[k]);
        c64 arr[3], aii[3];
#pragma unroll
        for (int k = 0; k < 3; k++) { arr[k] = pk(ar[k], ar[k]); aii[k] = pk(ai[k], ai[k]); }
#pragma unroll
        for (int c = 0; c < 3; c++) {
            c64 b0 = B.m[MODE == 1 ? c * 3 + 0 : 0 * 3 + c];
            c64 acc1 = mul2(arr[0], b0);
            c64 acc2 = mul2(aii[0], b0);
#pragma unroll
            for (int k = 1; k < 3; k++) {
                c64 b = B.m[MODE == 1 ? c * 3 + k : k * 3 + c];
                acc1 = fma2(arr[k], b, acc1);
                acc2 = fma2(aii[k], b, acc2);
            }
            float x1, y1, x2, y2;
            upk(acc1, x1, y1); upk(acc2, x2, y2);
            float cr, ci;
            if (MODE == 0)      { cr = x1 - y2; ci = y1 + x2; }
            else if (MODE == 1) { cr = x1 + y2; ci = x2 - y1; }
            else                { cr = x1 + y2; ci = y1 - x2; }
            C.m[r * 3 + c] = pk(cr, ci);
        }
    }
}

__device__ __forceinline__ void macc(C3 &F, const C3 &T, float c) {
    c64 cc = pk(c, c);
#pragma unroll
    for (int i = 0; i < 9; i++) F.m[i] = fma2(cc, T.m[i], F.m[i]);
}

// Forward staple (cf) + backward staple (cb) for one nu direction.
__device__ __forceinline__ void staple_pair(C3 &f,
        const float* __restrict__ xre, const float* __restrict__ xim,
        int b0p, int b0m, int bns, int bnsmu, int bnm, int bnmmu,
        float cf, float cb) {
    C3 A, B, C, T1, T2;
    mload(A, xre, xim, b0p);        // U0(s+nu)
    mload(B, xre, xim, bnsmu);      // Unu(s+mu)
    cmul<1>(T1, A, B);              // U0(s+nu) @ Unu(s+mu)^dag
    mload(C, xre, xim, bns);        // Unu(s)
    cmul<0>(T2, C, T1);
    macc(f, T2, cf);

    mload(A, xre, xim, bnm);        // Unu(s-nu)
    mload(B, xre, xim, b0m);        // U0(s-nu)
    cmul<2>(T1, A, B);              // Unu(s-nu)^dag @ U0(s-nu)
    mload(C, xre, xim, bnmmu);      // Unu(s-nu+mu)
    cmul<0>(T2, T1, C);
    macc(f, T2, cb);
}

__global__ __launch_bounds__(128) void stout_fused(
        const float* __restrict__ xre,
        const float* __restrict__ xim,
        const float* __restrict__ coeff,
        float2* __restrict__ out) {
    // ---- compute role: one even site per thread ----
    int tid = blockIdx.x * 128 + threadIdx.x;
    int xi = tid % 12; int r = tid / 12;
    int y = r % 24; r /= 24;
    int z = r % 24; r /= 24;
    int t = r;
    int par = (t + z + y) & 1;
    int x = 2 * xi + par;                    // (t+z+y+x) even

    int tp = (t + 1) % 24;
    int zp = (z + 1) % 24, zm = (z + 23) % 24;
    int yp = (y + 1) % 24, ym = (y + 23) % 24;
    int xp = (x + 1) % 24, xm = (x + 23) % 24;

    double* outd = (double*)out;

    // scale_coeff(coeff,0.75) with the /6 staple average folded in
    float c[6];
#pragma unroll
    for (int i = 0; i < 6; i++)
        c[i] = (0.47746482927568606f / 6.0f) * atanf(coeff[i]);

    C3 f;
#pragma unroll
    for (int i = 0; i < 9; i++) f.m[i] = 0ull;

    staple_pair(f, xre, xim,                     // nu = 1 (Z)
                IDX9(0,t,zp,y,x), IDX9(0,t,zm,y,x),
                IDX9(1,t,z,y,x),  IDX9(1,tp,z,y,x),
                IDX9(1,t,zm,y,x), IDX9(1,tp,zm,y,x),
                c[0], c[1]);
    staple_pair(f, xre, xim,                     // nu = 2 (Y)
                IDX9(0,t,z,yp,x), IDX9(0,t,z,ym,x),
                IDX9(2,t,z,y,x),  IDX9(2,tp,z,y,x),
                IDX9(2,t,z,ym,x), IDX9(2,tp,z,ym,x),
                c[2], c[3]);

    // ---- nu = 3 (X), inlined: also emits the odd-partner dir0 copy ----
    {
        C3 A, B, C, T1, T2;
        int b0p = IDX9(0,t,z,y,xp), b0m = IDX9(0,t,z,y,xm);
        mload(A, xre, xim, b0p);        // U0(s+x)
        if (par == 0) {
#pragma unroll
            for (int i = 0; i < 9; i++)
                __stcs(&outd[b0p + i], __longlong_as_double((long long)A.m[i]));
        }
        mload(B, xre, xim, IDX9(3,tp,z,y,x));   // x3(s+t)
        cmul<1>(T1, A, B);
        mload(C, xre, xim, IDX9(3,t,z,y,x));    // x3(s)
        cmul<0>(T2, C, T1);
        macc(f, T2, c[4]);

        mload(A, xre, xim, IDX9(3,t,z,y,xm));   // x3(s-x)
        mload(B, xre, xim, b0m);                // U0(s-x)
        if (par == 1) {
#pragma unroll
            for (int i = 0; i < 9; i++)
                __stcs(&outd[b0m + i], __longlong_as_double((long long)B.m[i]));
        }
        cmul<2>(T1, A, B);
        mload(C, xre, xim, IDX9(3,tp,z,y,xm));  // x3(s-x+t)
        cmul<0>(T2, T1, C);
        macc(f, T2, c[5]);
    }

    int b0 = IDX9(0, t, z, y, x);
    C3 U0; mload(U0, xre, xim, b0);

    // Z = projectTangent(f @ U0^dag) scaled by 2^-4
    C3 Mm; cmul<1>(Mm, f, U0);
    float mr[9], mi[9];
#pragma unroll
    for (int i = 0; i < 9; i++) upk(Mm.m[i], mr[i], mi[i]);
    const float s = 0.03125f;   // 0.5 * 2^-4
    float zre[9], zim[9];
#pragma unroll
    for (int rr = 0; rr < 3; rr++)
#pragma unroll
        for (int cc = 0; cc < 3; cc++) {
            zre[rr*3+cc] = s * (mr[rr*3+cc] - mr[cc*3+rr]);
            zim[rr*3+cc] = s * (mi[rr*3+cc] + mi[cc*3+rr]);
        }
    float tri = (zim[0] + zim[4] + zim[8]) * (1.0f / 3.0f);
    zim[0] -= tri; zim[4] -= tri; zim[8] -= tri;
    C3 Z;
#pragma unroll
    for (int i = 0; i < 9; i++) Z.m[i] = pk(zre[i], zim[i]);

    // ---- region-affine dirs1-3 copy: this block's own 256-site range ----
    // Block b covers site range [256b, 256(b+1)) -> floats [2304b, 2304(b+1))
    // within each of dirs 1..3. These are exactly the x1/x2/x3 center rows the
    // staple gathers just pulled -> loads hit hot L1/L2 lines. 576 float4 per
    // dir per array; 1728 jobs / 128 threads = 13.5 -> strided loop.
    // Placed before the (load-free) matexp so its FMA chain hides the misses.
    {
        const float4* re4 = (const float4*)xre;
        const float4* im4 = (const float4*)xim;
        float4* o4 = (float4*)out;
        int rb4 = blockIdx.x * 576;             // float4 offset within a dir
        for (int idx = threadIdx.x; idx < 1728; idx += 128) {
            int d = idx / 576;                  // 0..2 -> dirs 1..3
            int o = idx - d * 576;
            int i = (d + 1) * DIR_F4 + rb4 + o; // global float4 index
            float4 rr = re4[i], m = im4[i];
            __stcs(&o4[2*i],     make_float4(rr.x, m.x, rr.y, m.y));
            __stcs(&o4[2*i + 1], make_float4(rr.z, m.z, rr.w, m.w));
        }
    }

    // Horner Taylor, 8 terms: E = I + (Z@E)/k
    const c64 one = pk(1.0f, 0.0f);
    C3 E, T1;
#pragma unroll
    for (int i = 0; i < 9; i++) E.m[i] = (i % 4 == 0) ? one : 0ull;
#pragma unroll
    for (int k = 8; k >= 1; k--) {
        cmul<0>(T1, Z, E);
        float inv = 1.0f / (float)k;
        c64 inv2 = pk(inv, inv);
#pragma unroll
        for (int i = 0; i < 9; i++)
            E.m[i] = fma2(T1.m[i], inv2, (i % 4 == 0) ? one : 0ull);
    }
    // 4 squarings
#pragma unroll
    for (int sq = 0; sq < 4; sq++) { cmul<0>(T1, E, E); E = T1; }

    // y_mu = E @ U0 (even sites: xmu_fix = 0)
    C3 Y; cmul<0>(Y, E, U0);
#pragma unroll
    for (int i = 0; i < 9; i++)
        __stcs(&outd[b0 + i], __longlong_as_double((long long)Y.m[i]));
}

extern "C" void kernel_launch(void* const* d_in, const int* in_sizes, int n_in,
                              void* d_out, int out_size) {
    const float* xre   = (const float*)d_in[0];
    const float* xim   = (const float*)d_in[1];
    const float* coeff = (const float*)d_in[2];

    stout_fused<<<NCB, 128>>>(xre, xim, coeff, (float2*)d_out);
}